// round 16
// baseline (speedup 1.0000x reference)
#include <cuda_runtime.h>
#include <cuda_bf16.h>
#include <cstdint>
#include <stdint.h>
#include <math.h>

#define BATCH 4096

// ==================== scratch (device globals) ====================
__device__ __nv_bfloat16 g_f1h[(size_t)BATCH * 512];
__device__ __nv_bfloat16 g_f1l[(size_t)BATCH * 512];
__device__ float g_fi2a[BATCH * 256];
__device__ float g_fi2b[BATCH * 256];
__device__ float g_fi3[BATCH * 128];
__device__ float g_ft2[BATCH * 128];
__device__ float g_isp[BATCH * 128];
__device__ float g_ish[BATCH * 128];
__device__ float g_tsh[BATCH * 128];
__device__ float g_tsp[BATCH * 128];
__device__ __nv_bfloat16 g_fi3nh[BATCH * 128];
__device__ __nv_bfloat16 g_ft2nh[BATCH * 128];
__device__ __nv_bfloat16 g_ishnh[BATCH * 128];
__device__ __nv_bfloat16 g_tshnh[BATCH * 128];
__device__ float g_rs[2][5 * BATCH];
__device__ float g_cs[2][5 * BATCH];
__device__ double g_acc[4];            // [0]=clip1, [1]=clip2, [2]=S_t, [3]=S_i
__device__ int g_n0;

// ==================== helpers ====================
__device__ __forceinline__ uint32_t s2u(const void* p) {
    uint32_t a;
    asm("{ .reg .u64 t; cvta.to.shared.u64 t, %1; cvt.u32.u64 %0, t; }" : "=r"(a) : "l"(p));
    return a;
}
__device__ __forceinline__ void ldmx4(uint32_t (&r)[4], uint32_t addr) {
    asm volatile("ldmatrix.sync.aligned.m8n8.x4.shared.b16 {%0,%1,%2,%3}, [%4];"
                 : "=r"(r[0]), "=r"(r[1]), "=r"(r[2]), "=r"(r[3]) : "r"(addr));
}
__device__ __forceinline__ void mma16816(float (&d)[4], const uint32_t (&a)[4],
                                         uint32_t b0, uint32_t b1) {
    asm volatile(
        "mma.sync.aligned.m16n8k16.row.col.f32.bf16.bf16.f32 "
        "{%0,%1,%2,%3}, {%4,%5,%6,%7}, {%8,%9}, {%0,%1,%2,%3};"
        : "+f"(d[0]), "+f"(d[1]), "+f"(d[2]), "+f"(d[3])
        : "r"(a[0]), "r"(a[1]), "r"(a[2]), "r"(a[3]), "r"(b0), "r"(b1));
}
__device__ __forceinline__ float fexp(float x) {
    float t = x * 1.4426950408889634f;
    float fi = floorf(t);
    float f = t - fi;
    float p = 1.52527338e-5f;
    p = fmaf(p, f, 1.54035304e-4f);
    p = fmaf(p, f, 1.33335581e-3f);
    p = fmaf(p, f, 9.61812911e-3f);
    p = fmaf(p, f, 5.55041087e-2f);
    p = fmaf(p, f, 2.40226507e-1f);
    p = fmaf(p, f, 6.93147181e-1f);
    p = fmaf(p, f, 1.0f);
    int i = (int)fi;
    return __int_as_float((i + 127) << 23) * p;
}
__device__ __forceinline__ float wsum(float v) {
#pragma unroll
    for (int o = 16; o > 0; o >>= 1) v += __shfl_xor_sync(0xffffffffu, v, o);
    return v;
}
__device__ __forceinline__ float r4t(float v) {
    v += __shfl_xor_sync(0xffffffffu, v, 1);
    v += __shfl_xor_sync(0xffffffffu, v, 2);
    return v;
}
__device__ __forceinline__ float r8g(float v) {
    v += __shfl_xor_sync(0xffffffffu, v, 4);
    v += __shfl_xor_sync(0xffffffffu, v, 8);
    v += __shfl_xor_sync(0xffffffffu, v, 16);
    return v;
}
__device__ __forceinline__ void cvt8(const uint4& a, const uint4& b, uint4& hi, uint4& lo) {
    float f[8];
    *(uint4*)&f[0] = a;
    *(uint4*)&f[4] = b;
    unsigned short hs[8], ls[8];
#pragma unroll
    for (int j = 0; j < 8; j++) {
        __nv_bfloat16 h = __float2bfloat16(f[j]);
        __nv_bfloat16 l = __float2bfloat16(f[j] - __bfloat162float(h));
        hs[j] = __bfloat16_as_ushort(h);
        ls[j] = __bfloat16_as_ushort(l);
    }
    hi.x = (uint32_t)hs[0] | ((uint32_t)hs[1] << 16);
    hi.y = (uint32_t)hs[2] | ((uint32_t)hs[3] << 16);
    hi.z = (uint32_t)hs[4] | ((uint32_t)hs[5] << 16);
    hi.w = (uint32_t)hs[6] | ((uint32_t)hs[7] << 16);
    lo.x = (uint32_t)ls[0] | ((uint32_t)ls[1] << 16);
    lo.y = (uint32_t)ls[2] | ((uint32_t)ls[3] << 16);
    lo.z = (uint32_t)ls[4] | ((uint32_t)ls[5] << 16);
    lo.w = (uint32_t)ls[6] | ((uint32_t)ls[7] << 16);
}

// ==================== init ====================
__global__ void so2_init(const int* __restrict__ y) {
    int b = blockIdx.x, t = threadIdx.x;
    if (b == 0) {
        __shared__ int cnt[256];
        int c = 0;
        for (int j = t; j < BATCH; j += 256) c += (y[j] == 0) ? 1 : 0;
        cnt[t] = c;
        __syncthreads();
        for (int off = 128; off > 0; off >>= 1) {
            if (t < off) cnt[t] += cnt[t + off];
            __syncthreads();
        }
        if (t == 0) {
            g_n0 = cnt[0];
            g_acc[0] = 0.0; g_acc[1] = 0.0; g_acc[2] = 0.0; g_acc[3] = 0.0;
        }
    } else {
        int idx = (b - 1) * 2048 + t * 8;
        float* base = (idx < 2 * 5 * BATCH) ? &g_rs[0][0] : &g_cs[0][0];
        int off = (idx < 2 * 5 * BATCH) ? idx : idx - 2 * 5 * BATCH;
        float4 z = make_float4(0.f, 0.f, 0.f, 0.f);
        *(float4*)(base + off) = z;
        *(float4*)(base + off + 4) = z;
    }
}

// ==================== split HMMA GEMM, double-buffered ====================
// A/B as bf16 hi+lo (given, or converted inline from fp32). 3 MMAs ~ fp32.
// Dynamic SMEM: 2 buffers x 4 tiles x 10240B = 81920B.
template <bool A32, bool B32, bool RELU, int OUTM>
__global__ __launch_bounds__(256) void so2_gemm_mma(
    const float* __restrict__ Af, const __nv_bfloat16* __restrict__ Ah,
    const __nv_bfloat16* __restrict__ Al,
    const float* __restrict__ Bf, const __nv_bfloat16* __restrict__ Bh,
    const __nv_bfloat16* __restrict__ Bl,
    const float* __restrict__ bias,
    float* __restrict__ Cf0, float* __restrict__ Cf1,
    __nv_bfloat16* __restrict__ Ch, __nv_bfloat16* __restrict__ Cl,
    int N, int Kstride, int Kcomp)
{
    constexpr int LDSB = 80;
    constexpr int TILEB = 128 * LDSB;
    extern __shared__ __align__(16) char smem[];
    uint32_t sbase = s2u(smem);

    int tid = threadIdx.x, lane = tid & 31, wid = tid >> 5;
    int wrow = wid & 1, wcol = wid >> 1;
    int rbA = blockIdx.y * 128, rbB = blockIdx.x * 128;
    int kOff = blockIdx.z * Kcomp;
    float* Cf = (blockIdx.z == 0) ? Cf0 : Cf1;

    float acc[4][4][4];
#pragma unroll
    for (int a = 0; a < 4; a++)
#pragma unroll
        for (int b = 0; b < 4; b++)
#pragma unroll
            for (int c = 0; c < 4; c++) acc[a][b][c] = 0.f;

    uint4 stA[4], stB[4];
    auto fetch = [&](int k0) {
        int kk = kOff + k0;
#pragma unroll
        for (int g = 0; g < 2; g++) {
            int idx = tid + g * 256;
            int row = idx >> 2, seg = idx & 3;
            if (A32) {
                const float* p = Af + (size_t)(rbA + row) * Kstride + kk + seg * 8;
                stA[g * 2] = *(const uint4*)p;
                stA[g * 2 + 1] = *(const uint4*)(p + 4);
            } else {
                stA[g] = *(const uint4*)(Ah + (size_t)(rbA + row) * Kstride + kk + seg * 8);
                stA[2 + g] = *(const uint4*)(Al + (size_t)(rbA + row) * Kstride + kk + seg * 8);
            }
            if (B32) {
                const float* p = Bf + (size_t)(rbB + row) * Kstride + kk + seg * 8;
                stB[g * 2] = *(const uint4*)p;
                stB[g * 2 + 1] = *(const uint4*)(p + 4);
            } else {
                stB[g] = *(const uint4*)(Bh + (size_t)(rbB + row) * Kstride + kk + seg * 8);
                stB[2 + g] = *(const uint4*)(Bl + (size_t)(rbB + row) * Kstride + kk + seg * 8);
            }
        }
    };
    auto stash = [&](int buf) {
        char* base = smem + buf * 4 * TILEB;
#pragma unroll
        for (int g = 0; g < 2; g++) {
            int idx = tid + g * 256;
            int row = idx >> 2, seg = idx & 3;
            uint32_t off = (uint32_t)(row * LDSB + seg * 16);
            if (A32) {
                uint4 hi, lo;
                cvt8(stA[g * 2], stA[g * 2 + 1], hi, lo);
                *(uint4*)(base + 0 * TILEB + off) = hi;
                *(uint4*)(base + 1 * TILEB + off) = lo;
            } else {
                *(uint4*)(base + 0 * TILEB + off) = stA[g];
                *(uint4*)(base + 1 * TILEB + off) = stA[2 + g];
            }
            if (B32) {
                uint4 hi, lo;
                cvt8(stB[g * 2], stB[g * 2 + 1], hi, lo);
                *(uint4*)(base + 2 * TILEB + off) = hi;
                *(uint4*)(base + 3 * TILEB + off) = lo;
            } else {
                *(uint4*)(base + 2 * TILEB + off) = stB[g];
                *(uint4*)(base + 3 * TILEB + off) = stB[2 + g];
            }
        }
    };

    uint32_t aOff = (uint32_t)((wrow * 64 + (lane & 15)) * LDSB + (lane >> 4) * 16);
    uint32_t bOff = (uint32_t)((wcol * 32 + (lane & 15)) * LDSB + (lane >> 4) * 16);

    int NCH = Kcomp >> 5;
    fetch(0);
    stash(0);
    __syncthreads();
    for (int t = 0; t < NCH; t++) {
        int buf = t & 1;
        if (t + 1 < NCH) fetch((t + 1) << 5);
        uint32_t base = sbase + (uint32_t)(buf * 4 * TILEB);
        uint32_t aBase = base + aOff;
        uint32_t bBase = base + bOff;
#pragma unroll
        for (int p = 0; p < 2; p++) {
            uint32_t aH[4][4], aL[4][4], bH[2][4], bL[2][4];
#pragma unroll
            for (int mi = 0; mi < 4; mi++)
                ldmx4(aH[mi], aBase + 0 * TILEB + mi * 16 * LDSB + p * 32);
#pragma unroll
            for (int mi = 0; mi < 4; mi++)
                ldmx4(aL[mi], aBase + 1 * TILEB + mi * 16 * LDSB + p * 32);
#pragma unroll
            for (int np = 0; np < 2; np++)
                ldmx4(bH[np], bBase + 2 * TILEB + np * 16 * LDSB + p * 32);
#pragma unroll
            for (int np = 0; np < 2; np++)
                ldmx4(bL[np], bBase + 3 * TILEB + np * 16 * LDSB + p * 32);
#pragma unroll
            for (int mi = 0; mi < 4; mi++)
#pragma unroll
                for (int nt = 0; nt < 4; nt++) {
                    int np = nt >> 1, s = nt & 1;
                    mma16816(acc[mi][nt], aH[mi], bH[np][s], bH[np][2 + s]);
                    mma16816(acc[mi][nt], aH[mi], bL[np][s], bL[np][2 + s]);
                    mma16816(acc[mi][nt], aL[mi], bH[np][s], bH[np][2 + s]);
                }
        }
        if (t + 1 < NCH) stash(buf ^ 1);
        __syncthreads();
    }

    int g = lane >> 2, tig = lane & 3;
#pragma unroll
    for (int mi = 0; mi < 4; mi++)
#pragma unroll
        for (int q2 = 0; q2 < 2; q2++) {
            int row = rbA + wrow * 64 + mi * 16 + g + q2 * 8;
            size_t rowoff = (size_t)row * N;
#pragma unroll
            for (int nt = 0; nt < 4; nt++) {
                int col = rbB + wcol * 32 + nt * 8 + tig * 2;
                float v0 = acc[mi][nt][q2 * 2 + 0];
                float v1 = acc[mi][nt][q2 * 2 + 1];
                if (bias) { v0 += __ldg(bias + col); v1 += __ldg(bias + col + 1); }
                if (RELU) { v0 = fmaxf(v0, 0.f); v1 = fmaxf(v1, 0.f); }
                if (OUTM == 0) {
                    *(float2*)(Cf + rowoff + col) = make_float2(v0, v1);
                } else {
                    __nv_bfloat16 h0 = __float2bfloat16(v0), h1 = __float2bfloat16(v1);
                    __nv_bfloat16 l0 = __float2bfloat16(v0 - __bfloat162float(h0));
                    __nv_bfloat16 l1 = __float2bfloat16(v1 - __bfloat162float(h1));
                    uint32_t hp = (uint32_t)__bfloat16_as_ushort(h0) |
                                  ((uint32_t)__bfloat16_as_ushort(h1) << 16);
                    uint32_t lp = (uint32_t)__bfloat16_as_ushort(l0) |
                                  ((uint32_t)__bfloat16_as_ushort(l1) << 16);
                    *(uint32_t*)(Ch + rowoff + col) = hp;
                    *(uint32_t*)(Cl + rowoff + col) = lp;
                }
            }
        }
}

// ==================== fused clip GEMM (both losses, grid.z=2) ====================
__global__ __launch_bounds__(256) void so2_clip_gemm(
    const __nv_bfloat16* __restrict__ Ah0, const __nv_bfloat16* __restrict__ Bh0,
    const float* __restrict__ ls0,
    const __nv_bfloat16* __restrict__ Ah1, const __nv_bfloat16* __restrict__ Bh1,
    const float* __restrict__ ls1,
    const int* __restrict__ y)
{
    constexpr int LDSB = 80, TILEB = 128 * LDSB, K = 128;
    __shared__ __align__(16) char smem[2 * TILEB];
    __shared__ char ya[128], yb[128];
    uint32_t sbase = s2u(smem);

    int z = blockIdx.z;
    const __nv_bfloat16* Ah = z ? Ah1 : Ah0;
    const __nv_bfloat16* Bh = z ? Bh1 : Bh0;
    const float* log_scale = z ? ls1 : ls0;
    float* rs = &g_rs[z][0];
    float* cs = &g_cs[z][0];

    int tid = threadIdx.x, lane = tid & 31, wid = tid >> 5;
    int wrow = wid & 1, wcol = wid >> 1;
    int rbA = blockIdx.y * 128, rbB = blockIdx.x * 128;
    if (tid < 128) { ya[tid] = (char)y[rbA + tid]; yb[tid] = (char)y[rbB + tid]; }

    float acc[4][4][4];
#pragma unroll
    for (int a = 0; a < 4; a++)
#pragma unroll
        for (int b = 0; b < 4; b++)
#pragma unroll
            for (int c = 0; c < 4; c++) acc[a][b][c] = 0.f;

    uint4 st[2][2];
    auto fetch = [&](int k0) {
#pragma unroll
        for (int i = 0; i < 2; i++) {
            int idx = tid + i * 256;
            int row = idx >> 2, seg = idx & 3;
            st[0][i] = *(const uint4*)(Ah + (size_t)(rbA + row) * K + k0 + seg * 8);
            st[1][i] = *(const uint4*)(Bh + (size_t)(rbB + row) * K + k0 + seg * 8);
        }
    };
    auto stash = [&]() {
#pragma unroll
        for (int j = 0; j < 2; j++)
#pragma unroll
            for (int i = 0; i < 2; i++) {
                int idx = tid + i * 256;
                int row = idx >> 2, seg = idx & 3;
                *(uint4*)(smem + j * TILEB + row * LDSB + seg * 16) = st[j][i];
            }
    };
    uint32_t aBase = sbase + (uint32_t)((wrow * 64 + (lane & 15)) * LDSB + (lane >> 4) * 16);
    uint32_t bBase = sbase + (uint32_t)((32 * wcol + (lane & 15)) * LDSB + (lane >> 4) * 16) + TILEB;

    fetch(0);
#pragma unroll
    for (int t = 0; t < 4; t++) {
        stash();
        __syncthreads();
        if (t + 1 < 4) fetch((t + 1) << 5);
#pragma unroll
        for (int p = 0; p < 2; p++) {
            uint32_t aH[4][4], bH[2][4];
#pragma unroll
            for (int mi = 0; mi < 4; mi++)
                ldmx4(aH[mi], aBase + mi * 16 * LDSB + p * 32);
#pragma unroll
            for (int np = 0; np < 2; np++)
                ldmx4(bH[np], bBase + np * 16 * LDSB + p * 32);
#pragma unroll
            for (int mi = 0; mi < 4; mi++)
#pragma unroll
                for (int nt = 0; nt < 4; nt++) {
                    int np = nt >> 1, s = nt & 1;
                    mma16816(acc[mi][nt], aH[mi], bH[np][s], bH[np][2 + s]);
                }
        }
        __syncthreads();
    }

    float s = expf(*log_scale);
    int g = lane >> 2, tig = lane & 3;
    float cZ[8], cX[8], cP[8], cL[8], cLm[8];
#pragma unroll
    for (int i = 0; i < 8; i++) { cZ[i] = 0; cX[i] = 0; cP[i] = 0; cL[i] = 0; cLm[i] = 0; }

#pragma unroll
    for (int mi = 0; mi < 4; mi++)
#pragma unroll
        for (int q2 = 0; q2 < 2; q2++) {
            int rloc = wrow * 64 + mi * 16 + g + q2 * 8;
            char cr = ya[rloc];
            float rZ = 0, rX = 0, rP = 0, rL = 0, rLm = 0;
#pragma unroll
            for (int nt = 0; nt < 4; nt++)
#pragma unroll
                for (int cp = 0; cp < 2; cp++) {
                    int cloc = wcol * 32 + nt * 8 + tig * 2 + cp;
                    float m = acc[mi][nt][q2 * 2 + cp];
                    bool mt = (yb[cloc] == cr);
                    float lr = s * m;
                    float er = fexp(lr);
                    float ec = fexp(m);
                    rZ += er; rX += er * lr; rL += lr;
                    if (mt) { rP += er; rLm += lr; }
                    int ci = nt * 2 + cp;
                    cZ[ci] += ec; cX[ci] += ec * m; cL[ci] += m;
                    if (mt) { cP[ci] += ec; cLm[ci] += m; }
                }
            rZ = r4t(rZ); rX = r4t(rX); rP = r4t(rP); rL = r4t(rL); rLm = r4t(rLm);
            if (tig == 0) {
                int r = rbA + rloc;
                atomicAdd(rs + 0 * BATCH + r, rZ);
                atomicAdd(rs + 1 * BATCH + r, rX);
                atomicAdd(rs + 2 * BATCH + r, rP);
                atomicAdd(rs + 3 * BATCH + r, rL);
                atomicAdd(rs + 4 * BATCH + r, rLm);
            }
        }
#pragma unroll
    for (int ci = 0; ci < 8; ci++) {
        float zz = r8g(cZ[ci]), x = r8g(cX[ci]), pp = r8g(cP[ci]);
        float ll = r8g(cL[ci]), lm = r8g(cLm[ci]);
        if (g == 0) {
            int c = rbB + wcol * 32 + (ci >> 1) * 8 + tig * 2 + (ci & 1);
            atomicAdd(cs + 0 * BATCH + c, zz);
            atomicAdd(cs + 1 * BATCH + c, x);
            atomicAdd(cs + 2 * BATCH + c, pp);
            atomicAdd(cs + 3 * BATCH + c, ll);
            atomicAdd(cs + 4 * BATCH + c, lm);
        }
    }
}

// ==================== per-row softmax term ====================
__device__ __forceinline__ float so2_row_term(
    float Z, float X, float P, float L, float Lm, int c)
{
    float lse = logf(Z);
    float sum_p_logit = X / Z;
    float pmatch = P / Z;
    int n0 = g_n0;
    float nc = (c == 0) ? (float)n0 : (float)(BATCH - n0);
    float no = (float)BATCH - nc;
    float u = 1.0f / nc;
    float eu = expf(u);
    float denom = nc * eu + no;
    float lden = logf(denom);
    float lqm = u - lden;
    float lqn = -lden;
    float qm = eu / denom;
    float qn = 1.0f / denom;
    float sum_q_lq = nc * qm * lqm + no * qn * lqn;
    float sum_q_lp = qm * Lm + qn * (L - Lm) - lse;
    float sum_p_lp = sum_p_logit - lse;
    float sum_p_lq = lqm * pmatch + lqn * (1.0f - pmatch);
    return (sum_q_lq - sum_q_lp) + (sum_p_lp - sum_p_lq);
}

// ==================== clip finalize ====================
__global__ void so2_clip_final(const int* __restrict__ y) {
    int gi = blockIdx.x * 256 + threadIdx.x;
    int li = gi >> 13;
    int idx = gi & 8191;
    float term;
    {
        const float* st;
        int k;
        if (idx < BATCH) { st = g_rs[li]; k = idx; }
        else { st = g_cs[li]; k = idx - BATCH; }
        float Z = st[0 * BATCH + k], X = st[1 * BATCH + k], P = st[2 * BATCH + k];
        float L = st[3 * BATCH + k], Lm = st[4 * BATCH + k];
        term = so2_row_term(Z, X, P, L, Lm, y[k]);
    }
    __shared__ double sd[256];
    sd[threadIdx.x] = (double)term;
    __syncthreads();
    for (int off = 128; off > 0; off >>= 1) {
        if (threadIdx.x < off) sd[threadIdx.x] += sd[threadIdx.x + off];
        __syncthreads();
    }
    if (threadIdx.x == 0) atomicAdd(&g_acc[li], sd[0]);
}

// ==================== merged mid kernel: l3 (BM=16, 256 blocks) + tab MLP (128 blocks) ====================
// shared overlay: Ws [16][128] @0 (8192B); As @8192; F1 (tab) @10240
__device__ void mid_l3(char* sm, int bx,
                       const float* __restrict__ A, const float* __restrict__ A2,
                       const float* __restrict__ biasA,
                       const float* __restrict__ W, const float* __restrict__ bias,
                       float* __restrict__ Craw, __nv_bfloat16* __restrict__ Cnh)
{
    const int K = 256, BK = 16;
    float (*Ws)[128] = (float(*)[128])sm;
    float (*As)[16]  = (float(*)[16])(sm + 8192);
    int bm = bx * 16;
    int tid = threadIdx.x;
    int warp = tid >> 5, lane = tid & 31;
    int tr = warp * 2, tc = lane * 4;

    float acc[2][4];
#pragma unroll
    for (int i = 0; i < 2; i++)
#pragma unroll
        for (int j = 0; j < 4; j++) acc[i][j] = 0.f;

    float4 pa, pw[2];
    auto fetch = [&](int k0) {
        if (tid < 64) {
            int row = tid >> 2, kq = (tid & 3) * 4;
            float4 v = *(const float4*)(A + (size_t)(bm + row) * K + k0 + kq);
            float4 v2 = *(const float4*)(A2 + (size_t)(bm + row) * K + k0 + kq);
            float4 bb = *(const float4*)(biasA + k0 + kq);
            v.x = fmaxf(v.x + v2.x + bb.x, 0.f);
            v.y = fmaxf(v.y + v2.y + bb.y, 0.f);
            v.z = fmaxf(v.z + v2.z + bb.z, 0.f);
            v.w = fmaxf(v.w + v2.w + bb.w, 0.f);
            pa = v;
        }
#pragma unroll
        for (int i = 0; i < 2; i++) {
            int l = tid + i * 256;
            int row = l >> 2, kq = (l & 3) * 4;
            pw[i] = *(const float4*)(W + (size_t)row * K + k0 + kq);
        }
    };
    auto stash = [&]() {
        if (tid < 64) {
            int row = tid >> 2, kq = (tid & 3) * 4;
            As[kq + 0][row] = pa.x; As[kq + 1][row] = pa.y;
            As[kq + 2][row] = pa.z; As[kq + 3][row] = pa.w;
        }
#pragma unroll
        for (int i = 0; i < 2; i++) {
            int l = tid + i * 256;
            int row = l >> 2, kq = (l & 3) * 4;
            Ws[kq + 0][row] = pw[i].x; Ws[kq + 1][row] = pw[i].y;
            Ws[kq + 2][row] = pw[i].z; Ws[kq + 3][row] = pw[i].w;
        }
    };

    fetch(0);
    for (int t = 0; t < K / BK; t++) {
        stash();
        __syncthreads();
        if (t + 1 < K / BK) fetch((t + 1) * BK);
#pragma unroll
        for (int kk = 0; kk < BK; kk++) {
            float a0 = As[kk][tr], a1 = As[kk][tr + 1];
            float w[4];
            *(float4*)w = *(const float4*)&Ws[kk][tc];
#pragma unroll
            for (int j = 0; j < 4; j++) {
                acc[0][j] = fmaf(a0, w[j], acc[0][j]);
                acc[1][j] = fmaf(a1, w[j], acc[1][j]);
            }
        }
        __syncthreads();
    }

    float b[4];
#pragma unroll
    for (int j = 0; j < 4; j++) b[j] = bias[tc + j];
#pragma unroll
    for (int i = 0; i < 2; i++) {
        float v[4];
#pragma unroll
        for (int j = 0; j < 4; j++) v[j] = acc[i][j] + b[j];
        *(float4*)(Craw + (size_t)(bm + tr + i) * 128 + tc) =
            make_float4(v[0], v[1], v[2], v[3]);
        float s = v[0] * v[0] + v[1] * v[1] + v[2] * v[2] + v[3] * v[3];
        s = wsum(s);
        float inv = 1.0f / fmaxf(sqrtf(s), 1e-12f);
        unsigned short hs[4];
#pragma unroll
        for (int j = 0; j < 4; j++)
            hs[j] = __bfloat16_as_ushort(__float2bfloat16(v[j] * inv));
        uint2 u;
        u.x = (uint32_t)hs[0] | ((uint32_t)hs[1] << 16);
        u.y = (uint32_t)hs[2] | ((uint32_t)hs[3] << 16);
        *(uint2*)(Cnh + (size_t)(bm + tr + i) * 128 + tc) = u;
    }
}

__device__ void mid_tab(char* sm, int bx,
                        const float* __restrict__ T, const float* __restrict__ W1,
                        const float* __restrict__ B1,
                        const float* __restrict__ W2, const float* __restrict__ B2,
                        float* __restrict__ ft2, __nv_bfloat16* __restrict__ ft2nh)
{
    const int BM = 32, BK = 16, K1 = 49;
    float (*Ws)[128] = (float(*)[128])sm;              // [16][128]
    float (*As)[32]  = (float(*)[32])(sm + 8192);      // [16][32]
    float (*F1)[132] = (float(*)[132])(sm + 10240);    // [32][132]
    int bm = bx * BM;
    int tid = threadIdx.x;
    int warp = tid >> 5, lane = tid & 31;
    int tr = warp * 4, tc = lane * 4;

    float acc[4][4];
#pragma unroll
    for (int i = 0; i < 4; i++)
#pragma unroll
        for (int j = 0; j < 4; j++) acc[i][j] = 0.f;

    for (int t = 0; t < 4; t++) {
        int k0 = t * BK;
        for (int idx = tid; idx < BM * BK; idx += 256) {
            int r = idx >> 4, c = idx & 15;
            int gk = k0 + c;
            As[c][r] = (gk < K1) ? T[(size_t)(bm + r) * K1 + gk] : 0.f;
        }
        for (int idx = tid; idx < 128 * BK; idx += 256) {
            int r = idx >> 4, c = idx & 15;
            int gk = k0 + c;
            Ws[c][r] = (gk < K1) ? W1[(size_t)r * K1 + gk] : 0.f;
        }
        __syncthreads();
#pragma unroll
        for (int kk = 0; kk < BK; kk++) {
            float a[4], w[4];
            *(float4*)a = *(const float4*)&As[kk][tr];
            *(float4*)w = *(const float4*)&Ws[kk][tc];
#pragma unroll
            for (int i = 0; i < 4; i++)
#pragma unroll
                for (int j = 0; j < 4; j++) acc[i][j] = fmaf(a[i], w[j], acc[i][j]);
        }
        __syncthreads();
    }
#pragma unroll
    for (int i = 0; i < 4; i++)
#pragma unroll
        for (int j = 0; j < 4; j++)
            F1[tr + i][tc + j] = fmaxf(acc[i][j] + B1[tc + j], 0.f);

#pragma unroll
    for (int i = 0; i < 4; i++)
#pragma unroll
        for (int j = 0; j < 4; j++) acc[i][j] = 0.f;

    float4 pw[2];
    auto fetchW = [&](int k0) {
#pragma unroll
        for (int i = 0; i < 2; i++) {
            int l = tid + i * 256;
            int row = l >> 2, kq = (l & 3) * 4;
            pw[i] = *(const float4*)(W2 + (size_t)row * 128 + k0 + kq);
        }
    };
    auto stashW = [&]() {
#pragma unroll
        for (int i = 0; i < 2; i++) {
            int l = tid + i * 256;
            int row = l >> 2, kq = (l & 3) * 4;
            Ws[kq + 0][row] = pw[i].x; Ws[kq + 1][row] = pw[i].y;
            Ws[kq + 2][row] = pw[i].z; Ws[kq + 3][row] = pw[i].w;
        }
    };
    fetchW(0);
    for (int t = 0; t < 8; t++) {
        stashW();
        __syncthreads();
        if (t + 1 < 8) fetchW((t + 1) * BK);
#pragma unroll
        for (int kk = 0; kk < BK; kk++) {
            float a[4], w[4];
#pragma unroll
            for (int i = 0; i < 4; i++) a[i] = F1[tr + i][t * BK + kk];
            *(float4*)w = *(const float4*)&Ws[kk][tc];
#pragma unroll
            for (int i = 0; i < 4; i++)
#pragma unroll
                for (int j = 0; j < 4; j++) acc[i][j] = fmaf(a[i], w[j], acc[i][j]);
        }
        __syncthreads();
    }

    float b[4];
#pragma unroll
    for (int j = 0; j < 4; j++) b[j] = B2[tc + j];
    float v[4][4];
#pragma unroll
    for (int i = 0; i < 4; i++) {
#pragma unroll
        for (int j = 0; j < 4; j++) v[i][j] = acc[i][j] + b[j];
        *(float4*)(ft2 + (size_t)(bm + tr + i) * 128 + tc) =
            make_float4(v[i][0], v[i][1], v[i][2], v[i][3]);
    }
#pragma unroll
    for (int i = 0; i < 4; i++) {
        float s = v[i][0] * v[i][0] + v[i][1] * v[i][1] +
                  v[i][2] * v[i][2] + v[i][3] * v[i][3];
        s = wsum(s);
        float inv = 1.0f / fmaxf(sqrtf(s), 1e-12f);
        unsigned short hs[4];
#pragma unroll
        for (int j = 0; j < 4; j++)
            hs[j] = __bfloat16_as_ushort(__float2bfloat16(v[i][j] * inv));
        uint2 u;
        u.x = (uint32_t)hs[0] | ((uint32_t)hs[1] << 16);
        u.y = (uint32_t)hs[2] | ((uint32_t)hs[3] << 16);
        *(uint2*)(ft2nh + (size_t)(bm + tr + i) * 128 + tc) = u;
    }
}

__global__ __launch_bounds__(256) void so2_mid(
    const float* __restrict__ A, const float* __restrict__ A2,
    const float* __restrict__ biasA,
    const float* __restrict__ W, const float* __restrict__ bias,
    float* __restrict__ Craw, __nv_bfloat16* __restrict__ Cnh,
    const float* __restrict__ T, const float* __restrict__ W1,
    const float* __restrict__ B1,
    const float* __restrict__ W2, const float* __restrict__ B2,
    float* __restrict__ ft2, __nv_bfloat16* __restrict__ ft2nh)
{
    __shared__ __align__(16) char sm[27200];
    if (blockIdx.x < 256)
        mid_l3(sm, blockIdx.x, A, A2, biasA, W, bias, Craw, Cnh);
    else
        mid_tab(sm, blockIdx.x - 256, T, W1, B1, W2, B2, ft2, ft2nh);
}

// ==================== batched SS-heads GEMM (4 heads) + fused head outputs ====================
struct HeadsArgs {
    const float* A[4];
    const float* W[4];
    const float* b[4];
    float* raw[4];
    __nv_bfloat16* nh[4];
    const float* cw[4];
    const float* cb[4];
    int outoff[4];
};
__global__ __launch_bounds__(256) void so2_heads(HeadsArgs ha, float* __restrict__ out) {
    const int BM = 32, BK = 16, K = 128;
    int h = blockIdx.y;
    const float* A = ha.A[h];
    const float* W = ha.W[h];
    const float* bias = ha.b[h];
    float* Craw = ha.raw[h];
    __nv_bfloat16* Cnh = ha.nh[h];
    const float* cw = ha.cw[h];

    __shared__ float As[BK][BM];
    __shared__ float Ws[BK][128];
    int bm = blockIdx.x * BM;
    int tid = threadIdx.x;
    int warp = tid >> 5, lane = tid & 31;
    int tr = warp * 4, tc = lane * 4;

    float acc[4][4];
#pragma unroll
    for (int i = 0; i < 4; i++)
#pragma unroll
        for (int j = 0; j < 4; j++) acc[i][j] = 0.f;

    float4 pa, pw[2];
    auto fetch = [&](int k0) {
        if (tid < 128) {
            int row = tid >> 2, kq = (tid & 3) * 4;
            pa = *(const float4*)(A + (size_t)(bm + row) * K + k0 + kq);
        }
#pragma unroll
        for (int i = 0; i < 2; i++) {
            int l = tid + i * 256;
            int row = l >> 2, kq = (l & 3) * 4;
            pw[i] = *(const float4*)(W + (size_t)row * K + k0 + kq);
        }
    };
    auto stash = [&]() {
        if (tid < 128) {
            int row = tid >> 2, kq = (tid & 3) * 4;
            As[kq + 0][row] = pa.x; As[kq + 1][row] = pa.y;
            As[kq + 2][row] = pa.z; As[kq + 3][row] = pa.w;
        }
#pragma unroll
        for (int i = 0; i < 2; i++) {
            int l = tid + i * 256;
            int row = l >> 2, kq = (l & 3) * 4;
            Ws[kq + 0][row] = pw[i].x; Ws[kq + 1][row] = pw[i].y;
            Ws[kq + 2][row] = pw[i].z; Ws[kq + 3][row] = pw[i].w;
        }
    };

    fetch(0);
    for (int t = 0; t < K / BK; t++) {
        stash();
        __syncthreads();
        if (t + 1 < K / BK) fetch((t + 1) * BK);
#pragma unroll
        for (int kk = 0; kk < BK; kk++) {
            float a[4], w[4];
            *(float4*)a = *(const float4*)&As[kk][tr];
            *(float4*)w = *(const float4*)&Ws[kk][tc];
#pragma unroll
            for (int i = 0; i < 4; i++)
#pragma unroll
                for (int j = 0; j < 4; j++) acc[i][j] = fmaf(a[i], w[j], acc[i][j]);
        }
        __syncthreads();
    }

    float b4[4], cw4[4];
#pragma unroll
    for (int j = 0; j < 4; j++) { b4[j] = bias[tc + j]; cw4[j] = cw[tc + j]; }
    float v[4][4];
#pragma unroll
    for (int i = 0; i < 4; i++) {
#pragma unroll
        for (int j = 0; j < 4; j++) v[i][j] = acc[i][j] + b4[j];
        *(float4*)(Craw + (size_t)(bm + tr + i) * 128 + tc) =
            make_float4(v[i][0], v[i][1], v[i][2], v[i][3]);
        float d = v[i][0] * cw4[0] + v[i][1] * cw4[1] + v[i][2] * cw4[2] + v[i][3] * cw4[3];
        d = wsum(d);
        if (lane == 0) out[ha.outoff[h] + bm + tr + i] = d + ha.cb[h][0];
    }
    if (Cnh) {
#pragma unroll
        for (int i = 0; i < 4; i++) {
            float s = v[i][0] * v[i][0] + v[i][1] * v[i][1] +
                      v[i][2] * v[i][2] + v[i][3] * v[i][3];
            s = wsum(s);
            float inv = 1.0f / fmaxf(sqrtf(s), 1e-12f);
            unsigned short hs[4];
#pragma unroll
            for (int j = 0; j < 4; j++)
                hs[j] = __bfloat16_as_ushort(__float2bfloat16(v[i][j] * inv));
            uint2 u;
            u.x = (uint32_t)hs[0] | ((uint32_t)hs[1] << 16);
            u.y = (uint32_t)hs[2] | ((uint32_t)hs[3] << 16);
            *(uint2*)(Cnh + (size_t)(bm + tr + i) * 128 + tc) = u;
        }
    }
}

// ==================== sum over (A^T A) .* (B^T B), both pairs in one launch ====================
__global__ void so2_gram_pair(const float* __restrict__ A0, const float* __restrict__ B0,
                              const float* __restrict__ A1, const float* __restrict__ B1)
{
    const float* A = (blockIdx.z == 0) ? A0 : A1;
    const float* Bm = (blockIdx.z == 0) ? B0 : B1;
    int acc_idx = 2 + blockIdx.z;
    __shared__ float Au[16][17], Av[16][17], Bu[16][17], Bv[16][17];
    int u0 = blockIdx.x * 16, v0 = blockIdx.y * 16;
    int tx = threadIdx.x, ty = threadIdx.y;
    float ga = 0.f, gb = 0.f;
    for (int r0 = 0; r0 < BATCH; r0 += 16) {
        Au[ty][tx] = A[(r0 + ty) * 128 + u0 + tx];
        Av[ty][tx] = A[(r0 + ty) * 128 + v0 + tx];
        Bu[ty][tx] = Bm[(r0 + ty) * 128 + u0 + tx];
        Bv[ty][tx] = Bm[(r0 + ty) * 128 + v0 + tx];
        __syncthreads();
#pragma unroll
        for (int rr = 0; rr < 16; rr++) {
            ga += Au[rr][tx] * Av[rr][ty];
            gb += Bu[rr][tx] * Bv[rr][ty];
        }
        __syncthreads();
    }
    __shared__ float red[256];
    int t = ty * 16 + tx;
    red[t] = ga * gb;
    __syncthreads();
    for (int off = 128; off > 0; off >>= 1) {
        if (t < off) red[t] += red[t + off];
        __syncthreads();
    }
    if (t == 0) atomicAdd(&g_acc[acc_idx], (double)red[0]);
}

// ==================== final loss combine ====================
__global__ void so2_finalize(float* __restrict__ out) {
    double loss_sp = 0.5 * (sqrt(g_acc[2]) + sqrt(g_acc[3]));
    double loss1 = g_acc[0] / (4.0 * BATCH);
    double loss_sh = g_acc[1] / (4.0 * BATCH);
    out[0] = (float)((loss_sp + loss_sh + loss1) / 3.0);
}

// ==================== host driver ====================
extern "C" void kernel_launch(void* const* d_in, const int* in_sizes, int n_in,
                              void* d_out, int out_size) {
    const float* i_   = (const float*)d_in[0];
    const float* t_   = (const float*)d_in[1];
    const int*   y    = (const int*)d_in[2];
    const float* l1w  = (const float*)d_in[3];  const float* l1b = (const float*)d_in[4];
    const float* l2w  = (const float*)d_in[5];  const float* l2b = (const float*)d_in[6];
    const float* l3w  = (const float*)d_in[7];  const float* l3b = (const float*)d_in[8];
    const float* tl1w = (const float*)d_in[9];  const float* tl1b = (const float*)d_in[10];
    const float* tl2w = (const float*)d_in[11]; const float* tl2b = (const float*)d_in[12];
    const float* ispw = (const float*)d_in[13]; const float* ispb = (const float*)d_in[14];
    const float* ishw = (const float*)d_in[15]; const float* ishb = (const float*)d_in[16];
    const float* tshw = (const float*)d_in[17]; const float* tshb = (const float*)d_in[18];
    const float* tspw = (const float*)d_in[19]; const float* tspb = (const float*)d_in[20];
    const float* c1w  = (const float*)d_in[21]; const float* c1b = (const float*)d_in[22];
    const float* c2w  = (const float*)d_in[23]; const float* c2b = (const float*)d_in[24];
    const float* c3w  = (const float*)d_in[25]; const float* c3b = (const float*)d_in[26];
    const float* c4w  = (const float*)d_in[27]; const float* c4b = (const float*)d_in[28];
    const float* scale1 = (const float*)d_in[29];
    const float* scale2 = (const float*)d_in[30];
    float* out = (float*)d_out;

    float *pfi2a, *pfi2b, *pfi3, *pft2, *pisp, *pish, *ptsh, *ptsp;
    __nv_bfloat16 *pf1h, *pf1l, *pfi3nh, *pft2nh, *pishnh, *ptshnh;
    cudaGetSymbolAddress((void**)&pfi2a, g_fi2a);
    cudaGetSymbolAddress((void**)&pfi2b, g_fi2b);
    cudaGetSymbolAddress((void**)&pfi3, g_fi3);
    cudaGetSymbolAddress((void**)&pft2, g_ft2);
    cudaGetSymbolAddress((void**)&pisp, g_isp);
    cudaGetSymbolAddress((void**)&pish, g_ish);
    cudaGetSymbolAddress((void**)&ptsh, g_tsh);
    cudaGetSymbolAddress((void**)&ptsp, g_tsp);
    cudaGetSymbolAddress((void**)&pf1h, g_f1h);
    cudaGetSymbolAddress((void**)&pf1l, g_f1l);
    cudaGetSymbolAddress((void**)&pfi3nh, g_fi3nh);
    cudaGetSymbolAddress((void**)&pft2nh, g_ft2nh);
    cudaGetSymbolAddress((void**)&pishnh, g_ishnh);
    cudaGetSymbolAddress((void**)&ptshnh, g_tshnh);

    const int SMEM_BIG = 2 * 4 * 10240;   // 81920
    cudaFuncSetAttribute(so2_gemm_mma<true, true, true, 1>,
                         cudaFuncAttributeMaxDynamicSharedMemorySize, SMEM_BIG);
    cudaFuncSetAttribute(so2_gemm_mma<false, true, false, 0>,
                         cudaFuncAttributeMaxDynamicSharedMemorySize, SMEM_BIG);

    so2_init<<<41, 256>>>(y);

    // layer1: i (fp32, inline split) @ w1 (fp32, inline split) -> f1 bf16 hi/lo
    so2_gemm_mma<true, true, true, 1><<<dim3(4, 32, 1), 256, SMEM_BIG>>>(
        i_, nullptr, nullptr, l1w, nullptr, nullptr, l1b,
        nullptr, nullptr, pf1h, pf1l, 512, 2048, 2048);
    // layer2: f1 (bf16 pair) @ w2 (fp32, inline split), K-split z=2 -> fp32 partials
    so2_gemm_mma<false, true, false, 0><<<dim3(2, 32, 2), 256, SMEM_BIG>>>(
        nullptr, pf1h, pf1l, l2w, nullptr, nullptr, nullptr,
        pfi2a, pfi2b, nullptr, nullptr, 256, 512, 256);

    // merged l3 (256 blocks, BM=16) + tab MLP (128 blocks)
    so2_mid<<<384, 256>>>(pfi2a, pfi2b, l2b, l3w, l3b, pfi3, pfi3nh,
                          t_, tl1w, tl1b, tl2w, tl2b, pft2, pft2nh);

    // SS heads: one batched launch
    HeadsArgs ha;
    ha.A[0] = pfi3; ha.W[0] = ispw; ha.b[0] = ispb; ha.raw[0] = pisp; ha.nh[0] = nullptr;
    ha.cw[0] = c1w; ha.cb[0] = c1b; ha.outoff[0] = 1;
    ha.A[1] = pfi3; ha.W[1] = ishw; ha.b[1] = ishb; ha.raw[1] = pish; ha.nh[1] = pishnh;
    ha.cw[1] = c2w; ha.cb[1] = c2b; ha.outoff[1] = 1 + BATCH;
    ha.A[2] = pft2; ha.W[2] = tspw; ha.b[2] = tspb; ha.raw[2] = ptsp; ha.nh[2] = nullptr;
    ha.cw[2] = c4w; ha.cb[2] = c4b; ha.outoff[2] = 1 + 2 * BATCH;
    ha.A[3] = pft2; ha.W[3] = tshw; ha.b[3] = tshb; ha.raw[3] = ptsh; ha.nh[3] = ptshnh;
    ha.cw[3] = c3w; ha.cb[3] = c3b; ha.outoff[3] = 1 + 3 * BATCH;
    so2_heads<<<dim3(128, 4), 256>>>(ha, out);

    // both clip losses in one launch
    so2_clip_gemm<<<dim3(32, 32, 2), 256>>>(pfi3nh, pft2nh, scale1,
                                            pishnh, ptshnh, scale2, y);
    so2_clip_final<<<64, 256>>>(y);

    // separate loss via Gram trick
    so2_gram_pair<<<dim3(8, 8, 2), dim3(16, 16)>>>(ptsp, ptsh, pisp, pish);

    so2_finalize<<<1, 1>>>(out);
}

// round 17
// speedup vs baseline: 1.0721x; 1.0721x over previous
#include <cuda_runtime.h>
#include <cuda_bf16.h>
#include <cstdint>
#include <stdint.h>
#include <math.h>

#define BATCH 4096

// ==================== scratch (device globals) ====================
__device__ __nv_bfloat16 g_f1h[(size_t)BATCH * 512];
__device__ __nv_bfloat16 g_f1l[(size_t)BATCH * 512];
__device__ float g_fi2a[BATCH * 256];
__device__ float g_fi2b[BATCH * 256];
__device__ float g_fi3[BATCH * 128];
__device__ float g_ft2[BATCH * 128];
__device__ float g_isp[BATCH * 128];
__device__ float g_ish[BATCH * 128];
__device__ float g_tsh[BATCH * 128];
__device__ float g_tsp[BATCH * 128];
__device__ __nv_bfloat16 g_fi3nh[BATCH * 128];
__device__ __nv_bfloat16 g_ft2nh[BATCH * 128];
__device__ __nv_bfloat16 g_ishnh[BATCH * 128];
__device__ __nv_bfloat16 g_tshnh[BATCH * 128];
__device__ float g_rs[2][5 * BATCH];
__device__ float g_cs[2][5 * BATCH];
__device__ double g_acc[4];            // [0]=clip1, [1]=clip2, [2]=S_t, [3]=S_i
__device__ int g_n0;

// ==================== helpers ====================
__device__ __forceinline__ uint32_t s2u(const void* p) {
    uint32_t a;
    asm("{ .reg .u64 t; cvta.to.shared.u64 t, %1; cvt.u32.u64 %0, t; }" : "=r"(a) : "l"(p));
    return a;
}
__device__ __forceinline__ void ldmx4(uint32_t (&r)[4], uint32_t addr) {
    asm volatile("ldmatrix.sync.aligned.m8n8.x4.shared.b16 {%0,%1,%2,%3}, [%4];"
                 : "=r"(r[0]), "=r"(r[1]), "=r"(r[2]), "=r"(r[3]) : "r"(addr));
}
__device__ __forceinline__ void mma16816(float (&d)[4], const uint32_t (&a)[4],
                                         uint32_t b0, uint32_t b1) {
    asm volatile(
        "mma.sync.aligned.m16n8k16.row.col.f32.bf16.bf16.f32 "
        "{%0,%1,%2,%3}, {%4,%5,%6,%7}, {%8,%9}, {%0,%1,%2,%3};"
        : "+f"(d[0]), "+f"(d[1]), "+f"(d[2]), "+f"(d[3])
        : "r"(a[0]), "r"(a[1]), "r"(a[2]), "r"(a[3]), "r"(b0), "r"(b1));
}
__device__ __forceinline__ float fexp(float x) {
    float t = x * 1.4426950408889634f;
    float fi = floorf(t);
    float f = t - fi;
    float p = 1.52527338e-5f;
    p = fmaf(p, f, 1.54035304e-4f);
    p = fmaf(p, f, 1.33335581e-3f);
    p = fmaf(p, f, 9.61812911e-3f);
    p = fmaf(p, f, 5.55041087e-2f);
    p = fmaf(p, f, 2.40226507e-1f);
    p = fmaf(p, f, 6.93147181e-1f);
    p = fmaf(p, f, 1.0f);
    int i = (int)fi;
    return __int_as_float((i + 127) << 23) * p;
}
__device__ __forceinline__ float wsum(float v) {
#pragma unroll
    for (int o = 16; o > 0; o >>= 1) v += __shfl_xor_sync(0xffffffffu, v, o);
    return v;
}
__device__ __forceinline__ float r4t(float v) {
    v += __shfl_xor_sync(0xffffffffu, v, 1);
    v += __shfl_xor_sync(0xffffffffu, v, 2);
    return v;
}
__device__ __forceinline__ float r8g(float v) {
    v += __shfl_xor_sync(0xffffffffu, v, 4);
    v += __shfl_xor_sync(0xffffffffu, v, 8);
    v += __shfl_xor_sync(0xffffffffu, v, 16);
    return v;
}
__device__ __forceinline__ void cvt8(const uint4& a, const uint4& b, uint4& hi, uint4& lo) {
    float f[8];
    *(uint4*)&f[0] = a;
    *(uint4*)&f[4] = b;
    unsigned short hs[8], ls[8];
#pragma unroll
    for (int j = 0; j < 8; j++) {
        __nv_bfloat16 h = __float2bfloat16(f[j]);
        __nv_bfloat16 l = __float2bfloat16(f[j] - __bfloat162float(h));
        hs[j] = __bfloat16_as_ushort(h);
        ls[j] = __bfloat16_as_ushort(l);
    }
    hi.x = (uint32_t)hs[0] | ((uint32_t)hs[1] << 16);
    hi.y = (uint32_t)hs[2] | ((uint32_t)hs[3] << 16);
    hi.z = (uint32_t)hs[4] | ((uint32_t)hs[5] << 16);
    hi.w = (uint32_t)hs[6] | ((uint32_t)hs[7] << 16);
    lo.x = (uint32_t)ls[0] | ((uint32_t)ls[1] << 16);
    lo.y = (uint32_t)ls[2] | ((uint32_t)ls[3] << 16);
    lo.z = (uint32_t)ls[4] | ((uint32_t)ls[5] << 16);
    lo.w = (uint32_t)ls[6] | ((uint32_t)ls[7] << 16);
}

// ==================== init ====================
__global__ void so2_init(const int* __restrict__ y) {
    int b = blockIdx.x, t = threadIdx.x;
    if (b == 0) {
        __shared__ int cnt[256];
        int c = 0;
        for (int j = t; j < BATCH; j += 256) c += (y[j] == 0) ? 1 : 0;
        cnt[t] = c;
        __syncthreads();
        for (int off = 128; off > 0; off >>= 1) {
            if (t < off) cnt[t] += cnt[t + off];
            __syncthreads();
        }
        if (t == 0) {
            g_n0 = cnt[0];
            g_acc[0] = 0.0; g_acc[1] = 0.0; g_acc[2] = 0.0; g_acc[3] = 0.0;
        }
    } else {
        int idx = (b - 1) * 2048 + t * 8;
        float* base = (idx < 2 * 5 * BATCH) ? &g_rs[0][0] : &g_cs[0][0];
        int off = (idx < 2 * 5 * BATCH) ? idx : idx - 2 * 5 * BATCH;
        float4 z = make_float4(0.f, 0.f, 0.f, 0.f);
        *(float4*)(base + off) = z;
        *(float4*)(base + off + 4) = z;
    }
}

// ==================== split HMMA GEMM (single-buffer static SMEM, 2 CTA/SM) ====================
template <bool A32, bool B32, bool RELU, int OUTM>
__global__ __launch_bounds__(256) void so2_gemm_mma(
    const float* __restrict__ Af, const __nv_bfloat16* __restrict__ Ah,
    const __nv_bfloat16* __restrict__ Al,
    const float* __restrict__ Bf, const __nv_bfloat16* __restrict__ Bh,
    const __nv_bfloat16* __restrict__ Bl,
    const float* __restrict__ bias,
    float* __restrict__ Cf0, float* __restrict__ Cf1,
    __nv_bfloat16* __restrict__ Ch, __nv_bfloat16* __restrict__ Cl,
    int N, int Kstride, int Kcomp)
{
    constexpr int LDSB = 80;
    constexpr int TILEB = 128 * LDSB;
    __shared__ __align__(16) char smem[4 * TILEB];
    uint32_t sbase = s2u(smem);

    int tid = threadIdx.x, lane = tid & 31, wid = tid >> 5;
    int wrow = wid & 1, wcol = wid >> 1;
    int rbA = blockIdx.y * 128, rbB = blockIdx.x * 128;
    int kOff = blockIdx.z * Kcomp;
    float* Cf = (blockIdx.z == 0) ? Cf0 : Cf1;

    float acc[4][4][4];
#pragma unroll
    for (int a = 0; a < 4; a++)
#pragma unroll
        for (int b = 0; b < 4; b++)
#pragma unroll
            for (int c = 0; c < 4; c++) acc[a][b][c] = 0.f;

    uint4 stA[4], stB[4];
    auto fetch = [&](int k0) {
        int kk = kOff + k0;
#pragma unroll
        for (int g = 0; g < 2; g++) {
            int idx = tid + g * 256;
            int row = idx >> 2, seg = idx & 3;
            if (A32) {
                const float* p = Af + (size_t)(rbA + row) * Kstride + kk + seg * 8;
                stA[g * 2] = *(const uint4*)p;
                stA[g * 2 + 1] = *(const uint4*)(p + 4);
            } else {
                stA[g] = *(const uint4*)(Ah + (size_t)(rbA + row) * Kstride + kk + seg * 8);
                stA[2 + g] = *(const uint4*)(Al + (size_t)(rbA + row) * Kstride + kk + seg * 8);
            }
            if (B32) {
                const float* p = Bf + (size_t)(rbB + row) * Kstride + kk + seg * 8;
                stB[g * 2] = *(const uint4*)p;
                stB[g * 2 + 1] = *(const uint4*)(p + 4);
            } else {
                stB[g] = *(const uint4*)(Bh + (size_t)(rbB + row) * Kstride + kk + seg * 8);
                stB[2 + g] = *(const uint4*)(Bl + (size_t)(rbB + row) * Kstride + kk + seg * 8);
            }
        }
    };
    auto stash = [&]() {
#pragma unroll
        for (int g = 0; g < 2; g++) {
            int idx = tid + g * 256;
            int row = idx >> 2, seg = idx & 3;
            uint32_t off = (uint32_t)(row * LDSB + seg * 16);
            if (A32) {
                uint4 hi, lo;
                cvt8(stA[g * 2], stA[g * 2 + 1], hi, lo);
                *(uint4*)(smem + 0 * TILEB + off) = hi;
                *(uint4*)(smem + 1 * TILEB + off) = lo;
            } else {
                *(uint4*)(smem + 0 * TILEB + off) = stA[g];
                *(uint4*)(smem + 1 * TILEB + off) = stA[2 + g];
            }
            if (B32) {
                uint4 hi, lo;
                cvt8(stB[g * 2], stB[g * 2 + 1], hi, lo);
                *(uint4*)(smem + 2 * TILEB + off) = hi;
                *(uint4*)(smem + 3 * TILEB + off) = lo;
            } else {
                *(uint4*)(smem + 2 * TILEB + off) = stB[g];
                *(uint4*)(smem + 3 * TILEB + off) = stB[2 + g];
            }
        }
    };

    uint32_t aBase = sbase + (uint32_t)((wrow * 64 + (lane & 15)) * LDSB + (lane >> 4) * 16);
    uint32_t bBase = sbase + (uint32_t)((wcol * 32 + (lane & 15)) * LDSB + (lane >> 4) * 16);

    int NCH = Kcomp >> 5;
    fetch(0);
    for (int t = 0; t < NCH; t++) {
        stash();
        __syncthreads();
        if (t + 1 < NCH) fetch((t + 1) << 5);
#pragma unroll
        for (int p = 0; p < 2; p++) {
            uint32_t aH[4][4], aL[4][4], bH[2][4], bL[2][4];
#pragma unroll
            for (int mi = 0; mi < 4; mi++)
                ldmx4(aH[mi], aBase + 0 * TILEB + mi * 16 * LDSB + p * 32);
#pragma unroll
            for (int mi = 0; mi < 4; mi++)
                ldmx4(aL[mi], aBase + 1 * TILEB + mi * 16 * LDSB + p * 32);
#pragma unroll
            for (int np = 0; np < 2; np++)
                ldmx4(bH[np], bBase + 2 * TILEB + np * 16 * LDSB + p * 32);
#pragma unroll
            for (int np = 0; np < 2; np++)
                ldmx4(bL[np], bBase + 3 * TILEB + np * 16 * LDSB + p * 32);
#pragma unroll
            for (int mi = 0; mi < 4; mi++)
#pragma unroll
                for (int nt = 0; nt < 4; nt++) {
                    int np = nt >> 1, s = nt & 1;
                    mma16816(acc[mi][nt], aH[mi], bH[np][s], bH[np][2 + s]);
                    mma16816(acc[mi][nt], aH[mi], bL[np][s], bL[np][2 + s]);
                    mma16816(acc[mi][nt], aL[mi], bH[np][s], bH[np][2 + s]);
                }
        }
        __syncthreads();
    }

    int g = lane >> 2, tig = lane & 3;
#pragma unroll
    for (int mi = 0; mi < 4; mi++)
#pragma unroll
        for (int q2 = 0; q2 < 2; q2++) {
            int row = rbA + wrow * 64 + mi * 16 + g + q2 * 8;
            size_t rowoff = (size_t)row * N;
#pragma unroll
            for (int nt = 0; nt < 4; nt++) {
                int col = rbB + wcol * 32 + nt * 8 + tig * 2;
                float v0 = acc[mi][nt][q2 * 2 + 0];
                float v1 = acc[mi][nt][q2 * 2 + 1];
                if (bias) { v0 += __ldg(bias + col); v1 += __ldg(bias + col + 1); }
                if (RELU) { v0 = fmaxf(v0, 0.f); v1 = fmaxf(v1, 0.f); }
                if (OUTM == 0) {
                    *(float2*)(Cf + rowoff + col) = make_float2(v0, v1);
                } else {
                    __nv_bfloat16 h0 = __float2bfloat16(v0), h1 = __float2bfloat16(v1);
                    __nv_bfloat16 l0 = __float2bfloat16(v0 - __bfloat162float(h0));
                    __nv_bfloat16 l1 = __float2bfloat16(v1 - __bfloat162float(h1));
                    uint32_t hp = (uint32_t)__bfloat16_as_ushort(h0) |
                                  ((uint32_t)__bfloat16_as_ushort(h1) << 16);
                    uint32_t lp = (uint32_t)__bfloat16_as_ushort(l0) |
                                  ((uint32_t)__bfloat16_as_ushort(l1) << 16);
                    *(uint32_t*)(Ch + rowoff + col) = hp;
                    *(uint32_t*)(Cl + rowoff + col) = lp;
                }
            }
        }
}

// ==================== fused clip GEMM (both losses, grid.z=2) ====================
__global__ __launch_bounds__(256) void so2_clip_gemm(
    const __nv_bfloat16* __restrict__ Ah0, const __nv_bfloat16* __restrict__ Bh0,
    const float* __restrict__ ls0,
    const __nv_bfloat16* __restrict__ Ah1, const __nv_bfloat16* __restrict__ Bh1,
    const float* __restrict__ ls1,
    const int* __restrict__ y)
{
    constexpr int LDSB = 80, TILEB = 128 * LDSB, K = 128;
    __shared__ __align__(16) char smem[2 * TILEB];
    __shared__ char ya[128], yb[128];
    uint32_t sbase = s2u(smem);

    int z = blockIdx.z;
    const __nv_bfloat16* Ah = z ? Ah1 : Ah0;
    const __nv_bfloat16* Bh = z ? Bh1 : Bh0;
    const float* log_scale = z ? ls1 : ls0;
    float* rs = &g_rs[z][0];
    float* cs = &g_cs[z][0];

    int tid = threadIdx.x, lane = tid & 31, wid = tid >> 5;
    int wrow = wid & 1, wcol = wid >> 1;
    int rbA = blockIdx.y * 128, rbB = blockIdx.x * 128;
    if (tid < 128) { ya[tid] = (char)y[rbA + tid]; yb[tid] = (char)y[rbB + tid]; }

    float acc[4][4][4];
#pragma unroll
    for (int a = 0; a < 4; a++)
#pragma unroll
        for (int b = 0; b < 4; b++)
#pragma unroll
            for (int c = 0; c < 4; c++) acc[a][b][c] = 0.f;

    uint4 st[2][2];
    auto fetch = [&](int k0) {
#pragma unroll
        for (int i = 0; i < 2; i++) {
            int idx = tid + i * 256;
            int row = idx >> 2, seg = idx & 3;
            st[0][i] = *(const uint4*)(Ah + (size_t)(rbA + row) * K + k0 + seg * 8);
            st[1][i] = *(const uint4*)(Bh + (size_t)(rbB + row) * K + k0 + seg * 8);
        }
    };
    auto stash = [&]() {
#pragma unroll
        for (int j = 0; j < 2; j++)
#pragma unroll
            for (int i = 0; i < 2; i++) {
                int idx = tid + i * 256;
                int row = idx >> 2, seg = idx & 3;
                *(uint4*)(smem + j * TILEB + row * LDSB + seg * 16) = st[j][i];
            }
    };
    uint32_t aBase = sbase + (uint32_t)((wrow * 64 + (lane & 15)) * LDSB + (lane >> 4) * 16);
    uint32_t bBase = sbase + (uint32_t)((32 * wcol + (lane & 15)) * LDSB + (lane >> 4) * 16) + TILEB;

    fetch(0);
#pragma unroll
    for (int t = 0; t < 4; t++) {
        stash();
        __syncthreads();
        if (t + 1 < 4) fetch((t + 1) << 5);
#pragma unroll
        for (int p = 0; p < 2; p++) {
            uint32_t aH[4][4], bH[2][4];
#pragma unroll
            for (int mi = 0; mi < 4; mi++)
                ldmx4(aH[mi], aBase + mi * 16 * LDSB + p * 32);
#pragma unroll
            for (int np = 0; np < 2; np++)
                ldmx4(bH[np], bBase + np * 16 * LDSB + p * 32);
#pragma unroll
            for (int mi = 0; mi < 4; mi++)
#pragma unroll
                for (int nt = 0; nt < 4; nt++) {
                    int np = nt >> 1, s = nt & 1;
                    mma16816(acc[mi][nt], aH[mi], bH[np][s], bH[np][2 + s]);
                }
        }
        __syncthreads();
    }

    float s = expf(*log_scale);
    int g = lane >> 2, tig = lane & 3;
    float cZ[8], cX[8], cP[8], cL[8], cLm[8];
#pragma unroll
    for (int i = 0; i < 8; i++) { cZ[i] = 0; cX[i] = 0; cP[i] = 0; cL[i] = 0; cLm[i] = 0; }

#pragma unroll
    for (int mi = 0; mi < 4; mi++)
#pragma unroll
        for (int q2 = 0; q2 < 2; q2++) {
            int rloc = wrow * 64 + mi * 16 + g + q2 * 8;
            char cr = ya[rloc];
            float rZ = 0, rX = 0, rP = 0, rL = 0, rLm = 0;
#pragma unroll
            for (int nt = 0; nt < 4; nt++)
#pragma unroll
                for (int cp = 0; cp < 2; cp++) {
                    int cloc = wcol * 32 + nt * 8 + tig * 2 + cp;
                    float m = acc[mi][nt][q2 * 2 + cp];
                    bool mt = (yb[cloc] == cr);
                    float lr = s * m;
                    float er = fexp(lr);
                    float ec = fexp(m);
                    rZ += er; rX += er * lr; rL += lr;
                    if (mt) { rP += er; rLm += lr; }
                    int ci = nt * 2 + cp;
                    cZ[ci] += ec; cX[ci] += ec * m; cL[ci] += m;
                    if (mt) { cP[ci] += ec; cLm[ci] += m; }
                }
            rZ = r4t(rZ); rX = r4t(rX); rP = r4t(rP); rL = r4t(rL); rLm = r4t(rLm);
            if (tig == 0) {
                int r = rbA + rloc;
                atomicAdd(rs + 0 * BATCH + r, rZ);
                atomicAdd(rs + 1 * BATCH + r, rX);
                atomicAdd(rs + 2 * BATCH + r, rP);
                atomicAdd(rs + 3 * BATCH + r, rL);
                atomicAdd(rs + 4 * BATCH + r, rLm);
            }
        }
#pragma unroll
    for (int ci = 0; ci < 8; ci++) {
        float zz = r8g(cZ[ci]), x = r8g(cX[ci]), pp = r8g(cP[ci]);
        float ll = r8g(cL[ci]), lm = r8g(cLm[ci]);
        if (g == 0) {
            int c = rbB + wcol * 32 + (ci >> 1) * 8 + tig * 2 + (ci & 1);
            atomicAdd(cs + 0 * BATCH + c, zz);
            atomicAdd(cs + 1 * BATCH + c, x);
            atomicAdd(cs + 2 * BATCH + c, pp);
            atomicAdd(cs + 3 * BATCH + c, ll);
            atomicAdd(cs + 4 * BATCH + c, lm);
        }
    }
}

// ==================== per-row softmax term ====================
__device__ __forceinline__ float so2_row_term(
    float Z, float X, float P, float L, float Lm, int c)
{
    float lse = logf(Z);
    float sum_p_logit = X / Z;
    float pmatch = P / Z;
    int n0 = g_n0;
    float nc = (c == 0) ? (float)n0 : (float)(BATCH - n0);
    float no = (float)BATCH - nc;
    float u = 1.0f / nc;
    float eu = expf(u);
    float denom = nc * eu + no;
    float lden = logf(denom);
    float lqm = u - lden;
    float lqn = -lden;
    float qm = eu / denom;
    float qn = 1.0f / denom;
    float sum_q_lq = nc * qm * lqm + no * qn * lqn;
    float sum_q_lp = qm * Lm + qn * (L - Lm) - lse;
    float sum_p_lp = sum_p_logit - lse;
    float sum_p_lq = lqm * pmatch + lqn * (1.0f - pmatch);
    return (sum_q_lq - sum_q_lp) + (sum_p_lp - sum_p_lq);
}

// ==================== clip finalize ====================
__global__ void so2_clip_final(const int* __restrict__ y) {
    int gi = blockIdx.x * 256 + threadIdx.x;
    int li = gi >> 13;
    int idx = gi & 8191;
    float term;
    {
        const float* st;
        int k;
        if (idx < BATCH) { st = g_rs[li]; k = idx; }
        else { st = g_cs[li]; k = idx - BATCH; }
        float Z = st[0 * BATCH + k], X = st[1 * BATCH + k], P = st[2 * BATCH + k];
        float L = st[3 * BATCH + k], Lm = st[4 * BATCH + k];
        term = so2_row_term(Z, X, P, L, Lm, y[k]);
    }
    __shared__ double sd[256];
    sd[threadIdx.x] = (double)term;
    __syncthreads();
    for (int off = 128; off > 0; off >>= 1) {
        if (threadIdx.x < off) sd[threadIdx.x] += sd[threadIdx.x + off];
        __syncthreads();
    }
    if (threadIdx.x == 0) atomicAdd(&g_acc[li], sd[0]);
}

// ==================== merged mid kernel: l3 (BM=16, 256 blocks) + tab MLP (128 blocks) ====================
__device__ void mid_l3(char* sm, int bx,
                       const float* __restrict__ A, const float* __restrict__ A2,
                       const float* __restrict__ biasA,
                       const float* __restrict__ W, const float* __restrict__ bias,
                       float* __restrict__ Craw, __nv_bfloat16* __restrict__ Cnh)
{
    const int K = 256, BK = 16;
    float (*Ws)[128] = (float(*)[128])sm;
    float (*As)[16]  = (float(*)[16])(sm + 8192);
    int bm = bx * 16;
    int tid = threadIdx.x;
    int warp = tid >> 5, lane = tid & 31;
    int tr = warp * 2, tc = lane * 4;

    float acc[2][4];
#pragma unroll
    for (int i = 0; i < 2; i++)
#pragma unroll
        for (int j = 0; j < 4; j++) acc[i][j] = 0.f;

    float4 pa, pw[2];
    auto fetch = [&](int k0) {
        if (tid < 64) {
            int row = tid >> 2, kq = (tid & 3) * 4;
            float4 v = *(const float4*)(A + (size_t)(bm + row) * K + k0 + kq);
            float4 v2 = *(const float4*)(A2 + (size_t)(bm + row) * K + k0 + kq);
            float4 bb = *(const float4*)(biasA + k0 + kq);
            v.x = fmaxf(v.x + v2.x + bb.x, 0.f);
            v.y = fmaxf(v.y + v2.y + bb.y, 0.f);
            v.z = fmaxf(v.z + v2.z + bb.z, 0.f);
            v.w = fmaxf(v.w + v2.w + bb.w, 0.f);
            pa = v;
        }
#pragma unroll
        for (int i = 0; i < 2; i++) {
            int l = tid + i * 256;
            int row = l >> 2, kq = (l & 3) * 4;
            pw[i] = *(const float4*)(W + (size_t)row * K + k0 + kq);
        }
    };
    auto stash = [&]() {
        if (tid < 64) {
            int row = tid >> 2, kq = (tid & 3) * 4;
            As[kq + 0][row] = pa.x; As[kq + 1][row] = pa.y;
            As[kq + 2][row] = pa.z; As[kq + 3][row] = pa.w;
        }
#pragma unroll
        for (int i = 0; i < 2; i++) {
            int l = tid + i * 256;
            int row = l >> 2, kq = (l & 3) * 4;
            Ws[kq + 0][row] = pw[i].x; Ws[kq + 1][row] = pw[i].y;
            Ws[kq + 2][row] = pw[i].z; Ws[kq + 3][row] = pw[i].w;
        }
    };

    fetch(0);
    for (int t = 0; t < K / BK; t++) {
        stash();
        __syncthreads();
        if (t + 1 < K / BK) fetch((t + 1) * BK);
#pragma unroll
        for (int kk = 0; kk < BK; kk++) {
            float a0 = As[kk][tr], a1 = As[kk][tr + 1];
            float w[4];
            *(float4*)w = *(const float4*)&Ws[kk][tc];
#pragma unroll
            for (int j = 0; j < 4; j++) {
                acc[0][j] = fmaf(a0, w[j], acc[0][j]);
                acc[1][j] = fmaf(a1, w[j], acc[1][j]);
            }
        }
        __syncthreads();
    }

    float b[4];
#pragma unroll
    for (int j = 0; j < 4; j++) b[j] = bias[tc + j];
#pragma unroll
    for (int i = 0; i < 2; i++) {
        float v[4];
#pragma unroll
        for (int j = 0; j < 4; j++) v[j] = acc[i][j] + b[j];
        *(float4*)(Craw + (size_t)(bm + tr + i) * 128 + tc) =
            make_float4(v[0], v[1], v[2], v[3]);
        float s = v[0] * v[0] + v[1] * v[1] + v[2] * v[2] + v[3] * v[3];
        s = wsum(s);
        float inv = 1.0f / fmaxf(sqrtf(s), 1e-12f);
        unsigned short hs[4];
#pragma unroll
        for (int j = 0; j < 4; j++)
            hs[j] = __bfloat16_as_ushort(__float2bfloat16(v[j] * inv));
        uint2 u;
        u.x = (uint32_t)hs[0] | ((uint32_t)hs[1] << 16);
        u.y = (uint32_t)hs[2] | ((uint32_t)hs[3] << 16);
        *(uint2*)(Cnh + (size_t)(bm + tr + i) * 128 + tc) = u;
    }
}

__device__ void mid_tab(char* sm, int bx,
                        const float* __restrict__ T, const float* __restrict__ W1,
                        const float* __restrict__ B1,
                        const float* __restrict__ W2, const float* __restrict__ B2,
                        float* __restrict__ ft2, __nv_bfloat16* __restrict__ ft2nh)
{
    const int BM = 32, BK = 16, K1 = 49;
    float (*Ws)[128] = (float(*)[128])sm;
    float (*As)[32]  = (float(*)[32])(sm + 8192);
    float (*F1)[132] = (float(*)[132])(sm + 10240);
    int bm = bx * BM;
    int tid = threadIdx.x;
    int warp = tid >> 5, lane = tid & 31;
    int tr = warp * 4, tc = lane * 4;

    float acc[4][4];
#pragma unroll
    for (int i = 0; i < 4; i++)
#pragma unroll
        for (int j = 0; j < 4; j++) acc[i][j] = 0.f;

    for (int t = 0; t < 4; t++) {
        int k0 = t * BK;
        for (int idx = tid; idx < BM * BK; idx += 256) {
            int r = idx >> 4, c = idx & 15;
            int gk = k0 + c;
            As[c][r] = (gk < K1) ? T[(size_t)(bm + r) * K1 + gk] : 0.f;
        }
        for (int idx = tid; idx < 128 * BK; idx += 256) {
            int r = idx >> 4, c = idx & 15;
            int gk = k0 + c;
            Ws[c][r] = (gk < K1) ? W1[(size_t)r * K1 + gk] : 0.f;
        }
        __syncthreads();
#pragma unroll
        for (int kk = 0; kk < BK; kk++) {
            float a[4], w[4];
            *(float4*)a = *(const float4*)&As[kk][tr];
            *(float4*)w = *(const float4*)&Ws[kk][tc];
#pragma unroll
            for (int i = 0; i < 4; i++)
#pragma unroll
                for (int j = 0; j < 4; j++) acc[i][j] = fmaf(a[i], w[j], acc[i][j]);
        }
        __syncthreads();
    }
#pragma unroll
    for (int i = 0; i < 4; i++)
#pragma unroll
        for (int j = 0; j < 4; j++)
            F1[tr + i][tc + j] = fmaxf(acc[i][j] + B1[tc + j], 0.f);

#pragma unroll
    for (int i = 0; i < 4; i++)
#pragma unroll
        for (int j = 0; j < 4; j++) acc[i][j] = 0.f;

    float4 pw[2];
    auto fetchW = [&](int k0) {
#pragma unroll
        for (int i = 0; i < 2; i++) {
            int l = tid + i * 256;
            int row = l >> 2, kq = (l & 3) * 4;
            pw[i] = *(const float4*)(W2 + (size_t)row * 128 + k0 + kq);
        }
    };
    auto stashW = [&]() {
#pragma unroll
        for (int i = 0; i < 2; i++) {
            int l = tid + i * 256;
            int row = l >> 2, kq = (l & 3) * 4;
            Ws[kq + 0][row] = pw[i].x; Ws[kq + 1][row] = pw[i].y;
            Ws[kq + 2][row] = pw[i].z; Ws[kq + 3][row] = pw[i].w;
        }
    };
    fetchW(0);
    for (int t = 0; t < 8; t++) {
        stashW();
        __syncthreads();
        if (t + 1 < 8) fetchW((t + 1) * BK);
#pragma unroll
        for (int kk = 0; kk < BK; kk++) {
            float a[4], w[4];
#pragma unroll
            for (int i = 0; i < 4; i++) a[i] = F1[tr + i][t * BK + kk];
            *(float4*)w = *(const float4*)&Ws[kk][tc];
#pragma unroll
            for (int i = 0; i < 4; i++)
#pragma unroll
                for (int j = 0; j < 4; j++) acc[i][j] = fmaf(a[i], w[j], acc[i][j]);
        }
        __syncthreads();
    }

    float b[4];
#pragma unroll
    for (int j = 0; j < 4; j++) b[j] = B2[tc + j];
    float v[4][4];
#pragma unroll
    for (int i = 0; i < 4; i++) {
#pragma unroll
        for (int j = 0; j < 4; j++) v[i][j] = acc[i][j] + b[j];
        *(float4*)(ft2 + (size_t)(bm + tr + i) * 128 + tc) =
            make_float4(v[i][0], v[i][1], v[i][2], v[i][3]);
    }
#pragma unroll
    for (int i = 0; i < 4; i++) {
        float s = v[i][0] * v[i][0] + v[i][1] * v[i][1] +
                  v[i][2] * v[i][2] + v[i][3] * v[i][3];
        s = wsum(s);
        float inv = 1.0f / fmaxf(sqrtf(s), 1e-12f);
        unsigned short hs[4];
#pragma unroll
        for (int j = 0; j < 4; j++)
            hs[j] = __bfloat16_as_ushort(__float2bfloat16(v[i][j] * inv));
        uint2 u;
        u.x = (uint32_t)hs[0] | ((uint32_t)hs[1] << 16);
        u.y = (uint32_t)hs[2] | ((uint32_t)hs[3] << 16);
        *(uint2*)(ft2nh + (size_t)(bm + tr + i) * 128 + tc) = u;
    }
}

__global__ __launch_bounds__(256) void so2_mid(
    const float* __restrict__ A, const float* __restrict__ A2,
    const float* __restrict__ biasA,
    const float* __restrict__ W, const float* __restrict__ bias,
    float* __restrict__ Craw, __nv_bfloat16* __restrict__ Cnh,
    const float* __restrict__ T, const float* __restrict__ W1,
    const float* __restrict__ B1,
    const float* __restrict__ W2, const float* __restrict__ B2,
    float* __restrict__ ft2, __nv_bfloat16* __restrict__ ft2nh)
{
    __shared__ __align__(16) char sm[27200];
    if (blockIdx.x < 256)
        mid_l3(sm, blockIdx.x, A, A2, biasA, W, bias, Craw, Cnh);
    else
        mid_tab(sm, blockIdx.x - 256, T, W1, B1, W2, B2, ft2, ft2nh);
}

// ==================== batched SS-heads GEMM (4 heads) + fused head outputs ====================
struct HeadsArgs {
    const float* A[4];
    const float* W[4];
    const float* b[4];
    float* raw[4];
    __nv_bfloat16* nh[4];
    const float* cw[4];
    const float* cb[4];
    int outoff[4];
};
__global__ __launch_bounds__(256) void so2_heads(HeadsArgs ha, float* __restrict__ out) {
    const int BM = 32, BK = 16, K = 128;
    int h = blockIdx.y;
    const float* A = ha.A[h];
    const float* W = ha.W[h];
    const float* bias = ha.b[h];
    float* Craw = ha.raw[h];
    __nv_bfloat16* Cnh = ha.nh[h];
    const float* cw = ha.cw[h];

    __shared__ float As[BK][BM];
    __shared__ float Ws[BK][128];
    int bm = blockIdx.x * BM;
    int tid = threadIdx.x;
    int warp = tid >> 5, lane = tid & 31;
    int tr = warp * 4, tc = lane * 4;

    float acc[4][4];
#pragma unroll
    for (int i = 0; i < 4; i++)
#pragma unroll
        for (int j = 0; j < 4; j++) acc[i][j] = 0.f;

    float4 pa, pw[2];
    auto fetch = [&](int k0) {
        if (tid < 128) {
            int row = tid >> 2, kq = (tid & 3) * 4;
            pa = *(const float4*)(A + (size_t)(bm + row) * K + k0 + kq);
        }
#pragma unroll
        for (int i = 0; i < 2; i++) {
            int l = tid + i * 256;
            int row = l >> 2, kq = (l & 3) * 4;
            pw[i] = *(const float4*)(W + (size_t)row * K + k0 + kq);
        }
    };
    auto stash = [&]() {
        if (tid < 128) {
            int row = tid >> 2, kq = (tid & 3) * 4;
            As[kq + 0][row] = pa.x; As[kq + 1][row] = pa.y;
            As[kq + 2][row] = pa.z; As[kq + 3][row] = pa.w;
        }
#pragma unroll
        for (int i = 0; i < 2; i++) {
            int l = tid + i * 256;
            int row = l >> 2, kq = (l & 3) * 4;
            Ws[kq + 0][row] = pw[i].x; Ws[kq + 1][row] = pw[i].y;
            Ws[kq + 2][row] = pw[i].z; Ws[kq + 3][row] = pw[i].w;
        }
    };

    fetch(0);
    for (int t = 0; t < K / BK; t++) {
        stash();
        __syncthreads();
        if (t + 1 < K / BK) fetch((t + 1) * BK);
#pragma unroll
        for (int kk = 0; kk < BK; kk++) {
            float a[4], w[4];
            *(float4*)a = *(const float4*)&As[kk][tr];
            *(float4*)w = *(const float4*)&Ws[kk][tc];
#pragma unroll
            for (int i = 0; i < 4; i++)
#pragma unroll
                for (int j = 0; j < 4; j++) acc[i][j] = fmaf(a[i], w[j], acc[i][j]);
        }
        __syncthreads();
    }

    float b4[4], cw4[4];
#pragma unroll
    for (int j = 0; j < 4; j++) { b4[j] = bias[tc + j]; cw4[j] = cw[tc + j]; }
    float v[4][4];
#pragma unroll
    for (int i = 0; i < 4; i++) {
#pragma unroll
        for (int j = 0; j < 4; j++) v[i][j] = acc[i][j] + b4[j];
        *(float4*)(Craw + (size_t)(bm + tr + i) * 128 + tc) =
            make_float4(v[i][0], v[i][1], v[i][2], v[i][3]);
        float d = v[i][0] * cw4[0] + v[i][1] * cw4[1] + v[i][2] * cw4[2] + v[i][3] * cw4[3];
        d = wsum(d);
        if (lane == 0) out[ha.outoff[h] + bm + tr + i] = d + ha.cb[h][0];
    }
    if (Cnh) {
#pragma unroll
        for (int i = 0; i < 4; i++) {
            float s = v[i][0] * v[i][0] + v[i][1] * v[i][1] +
                      v[i][2] * v[i][2] + v[i][3] * v[i][3];
            s = wsum(s);
            float inv = 1.0f / fmaxf(sqrtf(s), 1e-12f);
            unsigned short hs[4];
#pragma unroll
            for (int j = 0; j < 4; j++)
                hs[j] = __bfloat16_as_ushort(__float2bfloat16(v[i][j] * inv));
            uint2 u;
            u.x = (uint32_t)hs[0] | ((uint32_t)hs[1] << 16);
            u.y = (uint32_t)hs[2] | ((uint32_t)hs[3] << 16);
            *(uint2*)(Cnh + (size_t)(bm + tr + i) * 128 + tc) = u;
        }
    }
}

// ==================== sum over (A^T A) .* (B^T B), both pairs in one launch ====================
__global__ void so2_gram_pair(const float* __restrict__ A0, const float* __restrict__ B0,
                              const float* __restrict__ A1, const float* __restrict__ B1)
{
    const float* A = (blockIdx.z == 0) ? A0 : A1;
    const float* Bm = (blockIdx.z == 0) ? B0 : B1;
    int acc_idx = 2 + blockIdx.z;
    __shared__ float Au[16][17], Av[16][17], Bu[16][17], Bv[16][17];
    int u0 = blockIdx.x * 16, v0 = blockIdx.y * 16;
    int tx = threadIdx.x, ty = threadIdx.y;
    float ga = 0.f, gb = 0.f;
    for (int r0 = 0; r0 < BATCH; r0 += 16) {
        Au[ty][tx] = A[(r0 + ty) * 128 + u0 + tx];
        Av[ty][tx] = A[(r0 + ty) * 128 + v0 + tx];
        Bu[ty][tx] = Bm[(r0 + ty) * 128 + u0 + tx];
        Bv[ty][tx] = Bm[(r0 + ty) * 128 + v0 + tx];
        __syncthreads();
#pragma unroll
        for (int rr = 0; rr < 16; rr++) {
            ga += Au[rr][tx] * Av[rr][ty];
            gb += Bu[rr][tx] * Bv[rr][ty];
        }
        __syncthreads();
    }
    __shared__ float red[256];
    int t = ty * 16 + tx;
    red[t] = ga * gb;
    __syncthreads();
    for (int off = 128; off > 0; off >>= 1) {
        if (t < off) red[t] += red[t + off];
        __syncthreads();
    }
    if (t == 0) atomicAdd(&g_acc[acc_idx], (double)red[0]);
}

// ==================== final loss combine ====================
__global__ void so2_finalize(float* __restrict__ out) {
    double loss_sp = 0.5 * (sqrt(g_acc[2]) + sqrt(g_acc[3]));
    double loss1 = g_acc[0] / (4.0 * BATCH);
    double loss_sh = g_acc[1] / (4.0 * BATCH);
    out[0] = (float)((loss_sp + loss_sh + loss1) / 3.0);
}

// ==================== host driver ====================
extern "C" void kernel_launch(void* const* d_in, const int* in_sizes, int n_in,
                              void* d_out, int out_size) {
    const float* i_   = (const float*)d_in[0];
    const float* t_   = (const float*)d_in[1];
    const int*   y    = (const int*)d_in[2];
    const float* l1w  = (const float*)d_in[3];  const float* l1b = (const float*)d_in[4];
    const float* l2w  = (const float*)d_in[5];  const float* l2b = (const float*)d_in[6];
    const float* l3w  = (const float*)d_in[7];  const float* l3b = (const float*)d_in[8];
    const float* tl1w = (const float*)d_in[9];  const float* tl1b = (const float*)d_in[10];
    const float* tl2w = (const float*)d_in[11]; const float* tl2b = (const float*)d_in[12];
    const float* ispw = (const float*)d_in[13]; const float* ispb = (const float*)d_in[14];
    const float* ishw = (const float*)d_in[15]; const float* ishb = (const float*)d_in[16];
    const float* tshw = (const float*)d_in[17]; const float* tshb = (const float*)d_in[18];
    const float* tspw = (const float*)d_in[19]; const float* tspb = (const float*)d_in[20];
    const float* c1w  = (const float*)d_in[21]; const float* c1b = (const float*)d_in[22];
    const float* c2w  = (const float*)d_in[23]; const float* c2b = (const float*)d_in[24];
    const float* c3w  = (const float*)d_in[25]; const float* c3b = (const float*)d_in[26];
    const float* c4w  = (const float*)d_in[27]; const float* c4b = (const float*)d_in[28];
    const float* scale1 = (const float*)d_in[29];
    const float* scale2 = (const float*)d_in[30];
    float* out = (float*)d_out;

    float *pfi2a, *pfi2b, *pfi3, *pft2, *pisp, *pish, *ptsh, *ptsp;
    __nv_bfloat16 *pf1h, *pf1l, *pfi3nh, *pft2nh, *pishnh, *ptshnh;
    cudaGetSymbolAddress((void**)&pfi2a, g_fi2a);
    cudaGetSymbolAddress((void**)&pfi2b, g_fi2b);
    cudaGetSymbolAddress((void**)&pfi3, g_fi3);
    cudaGetSymbolAddress((void**)&pft2, g_ft2);
    cudaGetSymbolAddress((void**)&pisp, g_isp);
    cudaGetSymbolAddress((void**)&pish, g_ish);
    cudaGetSymbolAddress((void**)&ptsh, g_tsh);
    cudaGetSymbolAddress((void**)&ptsp, g_tsp);
    cudaGetSymbolAddress((void**)&pf1h, g_f1h);
    cudaGetSymbolAddress((void**)&pf1l, g_f1l);
    cudaGetSymbolAddress((void**)&pfi3nh, g_fi3nh);
    cudaGetSymbolAddress((void**)&pft2nh, g_ft2nh);
    cudaGetSymbolAddress((void**)&pishnh, g_ishnh);
    cudaGetSymbolAddress((void**)&ptshnh, g_tshnh);

    so2_init<<<41, 256>>>(y);

    // layer1: i (fp32, inline split) @ w1 (fp32, inline split) -> f1 bf16 hi/lo
    so2_gemm_mma<true, true, true, 1><<<dim3(4, 32, 1), 256>>>(
        i_, nullptr, nullptr, l1w, nullptr, nullptr, l1b,
        nullptr, nullptr, pf1h, pf1l, 512, 2048, 2048);
    // layer2: f1 (bf16 pair) @ w2 (fp32, inline split), K-split z=2 -> fp32 partials
    so2_gemm_mma<false, true, false, 0><<<dim3(2, 32, 2), 256>>>(
        nullptr, pf1h, pf1l, l2w, nullptr, nullptr, nullptr,
        pfi2a, pfi2b, nullptr, nullptr, 256, 512, 256);

    // merged l3 (256 blocks, BM=16) + tab MLP (128 blocks)
    so2_mid<<<384, 256>>>(pfi2a, pfi2b, l2b, l3w, l3b, pfi3, pfi3nh,
                          t_, tl1w, tl1b, tl2w, tl2b, pft2, pft2nh);

    // SS heads: one batched launch
    HeadsArgs ha;
    ha.A[0] = pfi3; ha.W[0] = ispw; ha.b[0] = ispb; ha.raw[0] = pisp; ha.nh[0] = nullptr;
    ha.cw[0] = c1w; ha.cb[0] = c1b; ha.outoff[0] = 1;
    ha.A[1] = pfi3; ha.W[1] = ishw; ha.b[1] = ishb; ha.raw[1] = pish; ha.nh[1] = pishnh;
    ha.cw[1] = c2w; ha.cb[1] = c2b; ha.outoff[1] = 1 + BATCH;
    ha.A[2] = pft2; ha.W[2] = tspw; ha.b[2] = tspb; ha.raw[2] = ptsp; ha.nh[2] = nullptr;
    ha.cw[2] = c4w; ha.cb[2] = c4b; ha.outoff[2] = 1 + 2 * BATCH;
    ha.A[3] = pft2; ha.W[3] = tshw; ha.b[3] = tshb; ha.raw[3] = ptsh; ha.nh[3] = ptshnh;
    ha.cw[3] = c3w; ha.cb[3] = c3b; ha.outoff[3] = 1 + 3 * BATCH;
    so2_heads<<<dim3(128, 4), 256>>>(ha, out);

    // both clip losses in one launch
    so2_clip_gemm<<<dim3(32, 32, 2), 256>>>(pfi3nh, pft2nh, scale1,
                                            pishnh, ptshnh, scale2, y);
    so2_clip_final<<<64, 256>>>(y);

    // separate loss via Gram trick
    so2_gram_pair<<<dim3(8, 8, 2), dim3(16, 16)>>>(ptsp, ptsh, pisp, pish);

    so2_finalize<<<1, 1>>>(out);
}